// round 1
// baseline (speedup 1.0000x reference)
#include <cuda_runtime.h>

#define NV 5
#define NC 32
#define ND 48
#define NH 128
#define NW 160
#define HW (NH*NW)        /* 20480 */
#define DHW (ND*HW)       /* 983040 */
#define RATIO 8

// Scratch (device globals — no allocation allowed)
__device__ float g_feat[NV*HW*NC];        // (v, h, w, c) channels-last, 13.1 MB
__device__ float g_variance[(size_t)NC*DHW]; // (c, d, h, w), 126 MB
__device__ float g_pre[DHW];              // (d, h, w), 3.9 MB
__device__ float g_rot[NV][9];
__device__ float g_trans[NV][3];

// ---------------------------------------------------------------------------
// 1) Projection setup: combine intrinsics/extrinsics, invert ref 4x4,
//    per-view rot/trans of proj = src_comb @ inv(ref_comb).  Trivial work.
// ---------------------------------------------------------------------------
__global__ void proj_kernel(const float* __restrict__ proj) {
    if (threadIdx.x != 0) return;
    float comb[NV][16];
    for (int v = 0; v < NV; v++) {
        const float* E = proj + v*32;       // (4,4) extrinsic
        const float* P = proj + v*32 + 16;  // (4,4) intrinsic-embedded
        for (int r = 0; r < 3; r++)
            for (int c = 0; c < 4; c++) {
                float s = 0.f;
                for (int k = 0; k < 3; k++) s += P[r*4+k] * E[k*4+c];
                comb[v][r*4+c] = s;
            }
        for (int c = 0; c < 4; c++) comb[v][12+c] = E[12+c];
    }
    // Gauss-Jordan inverse of comb[0] with partial pivoting
    float a[4][8];
    for (int i = 0; i < 4; i++)
        for (int j = 0; j < 4; j++) { a[i][j] = comb[0][i*4+j]; a[i][4+j] = (i==j) ? 1.f : 0.f; }
    for (int col = 0; col < 4; col++) {
        int p = col;
        for (int r = col+1; r < 4; r++) if (fabsf(a[r][col]) > fabsf(a[p][col])) p = r;
        if (p != col) for (int j = 0; j < 8; j++) { float t = a[col][j]; a[col][j] = a[p][j]; a[p][j] = t; }
        float inv = 1.f / a[col][col];
        for (int j = 0; j < 8; j++) a[col][j] *= inv;
        for (int r = 0; r < 4; r++) if (r != col) {
            float f = a[r][col];
            for (int j = 0; j < 8; j++) a[r][j] -= f * a[col][j];
        }
    }
    for (int v = 1; v < NV; v++) {
        float Pm[16];
        for (int i = 0; i < 4; i++)
            for (int j = 0; j < 4; j++) {
                float s = 0.f;
                for (int k = 0; k < 4; k++) s += comb[v][i*4+k] * a[k][4+j];
                Pm[i*4+j] = s;
            }
        for (int i = 0; i < 3; i++) {
            for (int j = 0; j < 3; j++) g_rot[v][i*3+j] = Pm[i*4+j];
            g_trans[v][i] = Pm[i*4+3];
        }
    }
}

// ---------------------------------------------------------------------------
// 2) Transpose features (V,C,H,W) -> (V,H,W,C) so a bilinear tap reads
//    all 32 channels as one contiguous 128B line.
// ---------------------------------------------------------------------------
__global__ __launch_bounds__(256) void transpose_kernel(const float* __restrict__ f) {
    __shared__ float t[32][33];
    int w0 = blockIdx.x * 32, h = blockIdx.y, v = blockIdx.z;
    int tid = threadIdx.x;
    #pragma unroll
    for (int e = tid; e < 1024; e += 256) {
        int c = e >> 5, w = e & 31;
        t[c][w] = f[((size_t)(v*NC + c)*NH + h)*NW + w0 + w];
    }
    __syncthreads();
    #pragma unroll
    for (int e = tid; e < 1024; e += 256) {
        int w = e >> 5, c = e & 31;
        g_feat[((size_t)((v*NH + h)*NW) + w0 + w)*NC + c] = t[c][w];
    }
}

// ---------------------------------------------------------------------------
// 3) Homography warp + variance.  One CTA = 32 w-points at fixed (h, d).
//    Lane mapping: sub = lane>>3 selects 1 of 4 points per warp,
//    q = lane&7 selects a float4 channel-quad — so each warp LDG.128 pulls
//    4 complete 128B feature lines (perfect coalescing).
// ---------------------------------------------------------------------------
__global__ __launch_bounds__(256) void warpvar_kernel(const float* __restrict__ dvals) {
    int tid  = threadIdx.x;
    int lane = tid & 31, wid = tid >> 5;
    int sub = lane >> 3, q = lane & 7;
    int p  = wid * 4 + sub;              // point 0..31
    int w0 = blockIdx.x * 32;
    int h  = blockIdx.y;
    int d  = blockIdx.z;
    int w  = w0 + p;
    float dep = dvals[d];

    // reference view contribution (no warp, same for all d)
    const float4* f0 = (const float4*)(g_feat + (size_t)(h*NW + w)*NC) + q;
    float4 ref = *f0;
    float4 vs = ref;
    float4 vq = make_float4(ref.x*ref.x, ref.y*ref.y, ref.z*ref.z, ref.w*ref.w);

    float fw = (float)w, fh = (float)h;
    #pragma unroll
    for (int v = 1; v < NV; v++) {
        const float* R = g_rot[v];
        const float* T = g_trans[v];
        float px = (R[0]*fw + R[1]*fh + R[2]) * dep + T[0];
        float py = (R[3]*fw + R[4]*fh + R[5]) * dep + T[1];
        float pz = (R[6]*fw + R[7]*fh + R[8]) * dep + T[2];
        float rz = __fdividef(1.f, pz);
        float gx = px * rz, gy = py * rz;
        float x0f = floorf(gx), y0f = floorf(gy);
        float wx = gx - x0f, wy = gy - y0f;
        float x1f = x0f + 1.f, y1f = y0f + 1.f;
        float vx0 = (x0f >= 0.f && x0f <= (float)(NW-1)) ? 1.f : 0.f;
        float vx1 = (x1f >= 0.f && x1f <= (float)(NW-1)) ? 1.f : 0.f;
        float vy0 = (y0f >= 0.f && y0f <= (float)(NH-1)) ? 1.f : 0.f;
        float vy1 = (y1f >= 0.f && y1f <= (float)(NH-1)) ? 1.f : 0.f;
        float w00 = (1.f-wx)*(1.f-wy) * vx0 * vy0;
        float w10 = wx*(1.f-wy)       * vx1 * vy0;
        float w01 = (1.f-wx)*wy       * vx0 * vy1;
        float w11 = wx*wy             * vx1 * vy1;
        int x0 = (int)fminf(fmaxf(x0f, 0.f), (float)(NW-1));
        int x1 = (int)fminf(fmaxf(x1f, 0.f), (float)(NW-1));
        int y0 = (int)fminf(fmaxf(y0f, 0.f), (float)(NH-1));
        int y1 = (int)fminf(fmaxf(y1f, 0.f), (float)(NH-1));
        const float* base = g_feat + (size_t)v*HW*NC;
        float4 a  = ((const float4*)(base + (size_t)(y0*NW + x0)*NC))[q];
        float4 b  = ((const float4*)(base + (size_t)(y0*NW + x1)*NC))[q];
        float4 c4 = ((const float4*)(base + (size_t)(y1*NW + x0)*NC))[q];
        float4 e4 = ((const float4*)(base + (size_t)(y1*NW + x1)*NC))[q];
        float4 wv;
        wv.x = w00*a.x + w10*b.x + w01*c4.x + w11*e4.x;
        wv.y = w00*a.y + w10*b.y + w01*c4.y + w11*e4.y;
        wv.z = w00*a.z + w10*b.z + w01*c4.z + w11*e4.z;
        wv.w = w00*a.w + w10*b.w + w01*c4.w + w11*e4.w;
        vs.x += wv.x; vs.y += wv.y; vs.z += wv.z; vs.w += wv.w;
        vq.x += wv.x*wv.x; vq.y += wv.y*wv.y; vq.z += wv.z*wv.z; vq.w += wv.w*wv.w;
    }
    const float inv5 = 1.f / (float)NV;
    float4 var;
    float mx = vs.x*inv5, my = vs.y*inv5, mz = vs.z*inv5, mw = vs.w*inv5;
    var.x = vq.x*inv5 - mx*mx;
    var.y = vq.y*inv5 - my*my;
    var.z = vq.z*inv5 - mz*mz;
    var.w = vq.w*inv5 - mw*mw;

    // stage to smem, then coalesced (C,D,H,W) writes
    __shared__ float sv[32][33];
    sv[4*q+0][p] = var.x;
    sv[4*q+1][p] = var.y;
    sv[4*q+2][p] = var.z;
    sv[4*q+3][p] = var.w;
    __syncthreads();
    size_t obase = (size_t)d*HW + (size_t)h*NW + w0;
    #pragma unroll
    for (int e = tid; e < 1024; e += 256) {
        int c = e >> 5, wl = e & 31;
        g_variance[(size_t)c*DHW + obase + wl] = sv[c][wl];
    }
}

// ---------------------------------------------------------------------------
// 4) 3D conv (C=32 in, 1 out, 3x3x3, SAME).  CTA tile: 8(d) x 8(h) x 32(w)
//    outputs, smem-tiled per channel with a sliding-d register window.
// ---------------------------------------------------------------------------
__global__ __launch_bounds__(256) void conv_kernel(const float* __restrict__ Wreg) {
    __shared__ float s[10][10][34];
    __shared__ float sw[NC*27];
    int tx = threadIdx.x;          // 0..31 -> w
    int ty = threadIdx.y;          // 0..7  -> h
    int tid = ty*32 + tx;
    int wBase = blockIdx.x*32, hBase = blockIdx.y*8, dBase = blockIdx.z*8;

    for (int e = tid; e < NC*27; e += 256) sw[e] = Wreg[e];

    float acc[8];
    #pragma unroll
    for (int i = 0; i < 8; i++) acc[i] = 0.f;

    for (int c = 0; c < NC; c++) {
        __syncthreads();
        // load (10,10,34) input tile for channel c with zero padding
        for (int e = tid; e < 3400; e += 256) {
            int dd = e / 340; int rem = e - dd*340;
            int hh = rem / 34; int ww = rem - hh*34;
            int gd = dBase + dd - 1, gh = hBase + hh - 1, gw = wBase + ww - 1;
            float val = 0.f;
            if (gd >= 0 && gd < ND && gh >= 0 && gh < NH && gw >= 0 && gw < NW)
                val = g_variance[(size_t)c*DHW + (size_t)gd*HW + (size_t)gh*NW + gw];
            s[dd][hh][ww] = val;
        }
        __syncthreads();
        float wk[27];
        #pragma unroll
        for (int k = 0; k < 27; k++) wk[k] = sw[c*27 + k];
        #pragma unroll
        for (int dp = 0; dp < 10; dp++) {
            float n[9];
            #pragma unroll
            for (int kh = 0; kh < 3; kh++)
                #pragma unroll
                for (int kw = 0; kw < 3; kw++)
                    n[kh*3+kw] = s[dp][ty+kh][tx+kw];
            #pragma unroll
            for (int kd = 0; kd < 3; kd++) {
                int od = dp - kd;      // output plane receiving this input plane
                if (od >= 0 && od < 8) {
                    #pragma unroll
                    for (int k = 0; k < 9; k++) acc[od] += n[k] * wk[kd*9 + k];
                }
            }
        }
    }
    int hw = (hBase+ty)*NW + wBase + tx;
    #pragma unroll
    for (int od = 0; od < 8; od++)
        g_pre[(size_t)(dBase+od)*HW + hw] = acc[od];
}

// ---------------------------------------------------------------------------
// 5) Softmax over D + depth regression + confidence.  One thread per (h,w);
//    all 48 logits live in registers.
// ---------------------------------------------------------------------------
__global__ __launch_bounds__(256) void sdc_kernel(const float* __restrict__ dvals,
                                                  float* __restrict__ odepth,
                                                  float* __restrict__ oconf) {
    int idx = blockIdx.x*blockDim.x + threadIdx.x;
    if (idx >= HW) return;
    float p[ND];
    float mx = -1e30f;
    #pragma unroll
    for (int dd = 0; dd < ND; dd++) { p[dd] = g_pre[(size_t)dd*HW + idx]; mx = fmaxf(mx, p[dd]); }
    float s = 0.f;
    #pragma unroll
    for (int dd = 0; dd < ND; dd++) { p[dd] = expf(p[dd] - mx); s += p[dd]; }
    float inv = 1.f / s;
    float depth = 0.f, fi = 0.f;
    #pragma unroll
    for (int dd = 0; dd < ND; dd++) {
        float pr = p[dd] * inv;
        depth += pr * dvals[dd];
        fi    += pr * (float)dd;
    }
    int di = (int)fi;                       // trunc toward zero (fi >= 0)
    di = max(0, min(ND-1, di));
    float conf = 0.f;
    #pragma unroll
    for (int dd = 0; dd < ND; dd++)
        if (dd >= di-1 && dd <= di+2) conf += p[dd] * inv;
    odepth[idx] = depth;
    oconf[idx]  = conf;
}

// ---------------------------------------------------------------------------
// 6) Convex upsample x8.  One thread per (i, h, w) handles 8 j-subpixels:
//    mask loads coalesced across w, 32B contiguous stores per thread.
// ---------------------------------------------------------------------------
__global__ __launch_bounds__(256) void upsample_kernel(const float* __restrict__ mask,
                                                       const float* __restrict__ depth,
                                                       float* __restrict__ out) {
    int idx = blockIdx.x*blockDim.x + threadIdx.x;   // over RATIO*HW
    if (idx >= RATIO*HW) return;
    int i   = idx / HW;
    int rem = idx - i*HW;
    int h   = rem / NW;
    int w   = rem - h*NW;

    float nb[9];
    #pragma unroll
    for (int dy = 0; dy < 3; dy++)
        #pragma unroll
        for (int dx = 0; dx < 3; dx++) {
            int hh = h + dy - 1, ww = w + dx - 1;
            nb[dy*3+dx] = (hh >= 0 && hh < NH && ww >= 0 && ww < NW) ? depth[hh*NW + ww] : 0.f;
        }

    float val[8];
    #pragma unroll
    for (int j = 0; j < 8; j++) {
        float m[9]; float mx = -1e30f;
        #pragma unroll
        for (int k = 0; k < 9; k++) {
            m[k] = mask[(size_t)((k*8 + i)*8 + j)*HW + rem];
            mx = fmaxf(mx, m[k]);
        }
        float s = 0.f, acc = 0.f;
        #pragma unroll
        for (int k = 0; k < 9; k++) {
            float e = __expf(m[k] - mx);
            s += e; acc += e * nb[k];
        }
        val[j] = acc / s;
    }
    float* o = out + (size_t)(h*8 + i)*(NW*8) + w*8;
    float4* o4 = (float4*)o;
    o4[0] = make_float4(val[0], val[1], val[2], val[3]);
    o4[1] = make_float4(val[4], val[5], val[6], val[7]);
}

// ---------------------------------------------------------------------------
extern "C" void kernel_launch(void* const* d_in, const int* in_sizes, int n_in,
                              void* d_out, int out_size) {
    const float* features = (const float*)d_in[0];  // (V,B,C,H,W)
    const float* proj     = (const float*)d_in[1];  // (B,V,2,4,4)
    const float* dvals    = (const float*)d_in[2];  // (B,D)
    const float* mask     = (const float*)d_in[3];  // (B,576,H,W)
    const float* Wreg     = (const float*)d_in[4];  // (1,C,3,3,3)

    float* out       = (float*)d_out;
    float* out_depth = out + (size_t)NH*RATIO*NW*RATIO;   // after depth_up
    float* out_conf  = out_depth + HW;

    proj_kernel<<<1, 32>>>(proj);
    transpose_kernel<<<dim3(NW/32, NH, NV), 256>>>(features);
    warpvar_kernel<<<dim3(NW/32, NH, ND), 256>>>(dvals);
    conv_kernel<<<dim3(NW/32, NH/8, ND/8), dim3(32, 8)>>>(Wreg);
    sdc_kernel<<<HW/256, 256>>>(dvals, out_depth, out_conf);
    upsample_kernel<<<(RATIO*HW)/256, 256>>>(mask, out_depth, out);
}

// round 2
// speedup vs baseline: 1.0351x; 1.0351x over previous
#include <cuda_runtime.h>

#define NV 5
#define NC 32
#define ND 48
#define NH 128
#define NW 160
#define HW (NH*NW)        /* 20480 */
#define DHW (ND*HW)       /* 983040 */
#define RATIO 8

// Scratch (device globals — no allocation allowed)
__device__ float g_feat[NV*HW*NC];          // (v, h, w, c) channels-last, 13.1 MB
__device__ float g_A[(size_t)27*DHW];       // 27 tap-fields (j, d, h, w), 106 MB
__device__ float g_pre[DHW];                // (d, h, w), 3.9 MB
__device__ float g_rot[NV][9];
__device__ float g_trans[NV][3];

// ---------------------------------------------------------------------------
// 1) Projection setup (trivial)
// ---------------------------------------------------------------------------
__global__ void proj_kernel(const float* __restrict__ proj) {
    if (threadIdx.x != 0) return;
    float comb[NV][16];
    for (int v = 0; v < NV; v++) {
        const float* E = proj + v*32;
        const float* P = proj + v*32 + 16;
        for (int r = 0; r < 3; r++)
            for (int c = 0; c < 4; c++) {
                float s = 0.f;
                for (int k = 0; k < 3; k++) s += P[r*4+k] * E[k*4+c];
                comb[v][r*4+c] = s;
            }
        for (int c = 0; c < 4; c++) comb[v][12+c] = E[12+c];
    }
    float a[4][8];
    for (int i = 0; i < 4; i++)
        for (int j = 0; j < 4; j++) { a[i][j] = comb[0][i*4+j]; a[i][4+j] = (i==j) ? 1.f : 0.f; }
    for (int col = 0; col < 4; col++) {
        int p = col;
        for (int r = col+1; r < 4; r++) if (fabsf(a[r][col]) > fabsf(a[p][col])) p = r;
        if (p != col) for (int j = 0; j < 8; j++) { float t = a[col][j]; a[col][j] = a[p][j]; a[p][j] = t; }
        float inv = 1.f / a[col][col];
        for (int j = 0; j < 8; j++) a[col][j] *= inv;
        for (int r = 0; r < 4; r++) if (r != col) {
            float f = a[r][col];
            for (int j = 0; j < 8; j++) a[r][j] -= f * a[col][j];
        }
    }
    for (int v = 1; v < NV; v++) {
        float Pm[16];
        for (int i = 0; i < 4; i++)
            for (int j = 0; j < 4; j++) {
                float s = 0.f;
                for (int k = 0; k < 4; k++) s += comb[v][i*4+k] * a[k][4+j];
                Pm[i*4+j] = s;
            }
        for (int i = 0; i < 3; i++) {
            for (int j = 0; j < 3; j++) g_rot[v][i*3+j] = Pm[i*4+j];
            g_trans[v][i] = Pm[i*4+3];
        }
    }
}

// ---------------------------------------------------------------------------
// 2) Features (V,C,H,W) -> (V,H,W,C) channels-last
// ---------------------------------------------------------------------------
__global__ __launch_bounds__(256) void transpose_kernel(const float* __restrict__ f) {
    __shared__ float t[32][33];
    int w0 = blockIdx.x * 32, h = blockIdx.y, v = blockIdx.z;
    int tid = threadIdx.x;
    #pragma unroll
    for (int e = tid; e < 1024; e += 256) {
        int c = e >> 5, w = e & 31;
        t[c][w] = f[((size_t)(v*NC + c)*NH + h)*NW + w0 + w];
    }
    __syncthreads();
    #pragma unroll
    for (int e = tid; e < 1024; e += 256) {
        int w = e >> 5, c = e & 31;
        g_feat[((size_t)((v*NH + h)*NW) + w0 + w)*NC + c] = t[c][w];
    }
}

// ---------------------------------------------------------------------------
// 3) FUSED homography warp + variance + channel contraction.
//    Phase A: per-voxel variance (channels spread over 8 quad-lanes, LDG.128
//             pulls 4 complete 128B feature lines per warp instruction).
//    Phase B: A_j[w] = sum_c W[c][j] * var[c][w] as a warp-level GEMM:
//             warp `wid` owns taps {wid, wid+8, wid+16, wid+24}; lane l holds
//             W[c=l][j] in registers, broadcast per-c via shfl.
// ---------------------------------------------------------------------------
__global__ __launch_bounds__(256) void warpvar_kernel(const float* __restrict__ dvals,
                                                      const float* __restrict__ Wreg) {
    int tid  = threadIdx.x;
    int lane = tid & 31, wid = tid >> 5;
    int sub = lane >> 3, q = lane & 7;
    int p  = wid * 4 + sub;              // point 0..31
    int w0 = blockIdx.x * 32;
    int h  = blockIdx.y;
    int d  = blockIdx.z;
    int w  = w0 + p;
    float dep = dvals[d];

    // ---- Phase B weight preload (independent of Phase A, hides LDG) ----
    float wreg[4];
    #pragma unroll
    for (int jj = 0; jj < 4; jj++) {
        int j = wid + 8*jj;
        wreg[jj] = (j < 27) ? Wreg[lane*27 + j] : 0.f;
    }

    // ---- Phase A: variance for my 4 channels of voxel (h, w, d) ----
    const float4* f0 = (const float4*)(g_feat + (size_t)(h*NW + w)*NC) + q;
    float4 ref = *f0;
    float4 vs = ref;
    float4 vq = make_float4(ref.x*ref.x, ref.y*ref.y, ref.z*ref.z, ref.w*ref.w);

    float fw = (float)w, fh = (float)h;
    #pragma unroll
    for (int v = 1; v < NV; v++) {
        const float* R = g_rot[v];
        const float* T = g_trans[v];
        float px = (R[0]*fw + R[1]*fh + R[2]) * dep + T[0];
        float py = (R[3]*fw + R[4]*fh + R[5]) * dep + T[1];
        float pz = (R[6]*fw + R[7]*fh + R[8]) * dep + T[2];
        float rz = __fdividef(1.f, pz);
        float gx = px * rz, gy = py * rz;
        float x0f = floorf(gx), y0f = floorf(gy);
        float wx = gx - x0f, wy = gy - y0f;
        float x1f = x0f + 1.f, y1f = y0f + 1.f;
        float vx0 = (x0f >= 0.f && x0f <= (float)(NW-1)) ? 1.f : 0.f;
        float vx1 = (x1f >= 0.f && x1f <= (float)(NW-1)) ? 1.f : 0.f;
        float vy0 = (y0f >= 0.f && y0f <= (float)(NH-1)) ? 1.f : 0.f;
        float vy1 = (y1f >= 0.f && y1f <= (float)(NH-1)) ? 1.f : 0.f;
        float w00 = (1.f-wx)*(1.f-wy) * vx0 * vy0;
        float w10 = wx*(1.f-wy)       * vx1 * vy0;
        float w01 = (1.f-wx)*wy       * vx0 * vy1;
        float w11 = wx*wy             * vx1 * vy1;
        int x0 = (int)fminf(fmaxf(x0f, 0.f), (float)(NW-1));
        int x1 = (int)fminf(fmaxf(x1f, 0.f), (float)(NW-1));
        int y0 = (int)fminf(fmaxf(y0f, 0.f), (float)(NH-1));
        int y1 = (int)fminf(fmaxf(y1f, 0.f), (float)(NH-1));
        const float* base = g_feat + (size_t)v*HW*NC;
        float4 a  = ((const float4*)(base + (size_t)(y0*NW + x0)*NC))[q];
        float4 b  = ((const float4*)(base + (size_t)(y0*NW + x1)*NC))[q];
        float4 c4 = ((const float4*)(base + (size_t)(y1*NW + x0)*NC))[q];
        float4 e4 = ((const float4*)(base + (size_t)(y1*NW + x1)*NC))[q];
        float4 wv;
        wv.x = w00*a.x + w10*b.x + w01*c4.x + w11*e4.x;
        wv.y = w00*a.y + w10*b.y + w01*c4.y + w11*e4.y;
        wv.z = w00*a.z + w10*b.z + w01*c4.z + w11*e4.z;
        wv.w = w00*a.w + w10*b.w + w01*c4.w + w11*e4.w;
        vs.x += wv.x; vs.y += wv.y; vs.z += wv.z; vs.w += wv.w;
        vq.x += wv.x*wv.x; vq.y += wv.y*wv.y; vq.z += wv.z*wv.z; vq.w += wv.w*wv.w;
    }
    const float inv5 = 1.f / (float)NV;
    float4 var;
    float mx = vs.x*inv5, my = vs.y*inv5, mz = vs.z*inv5, mw = vs.w*inv5;
    var.x = vq.x*inv5 - mx*mx;
    var.y = vq.y*inv5 - my*my;
    var.z = vq.z*inv5 - mz*mz;
    var.w = vq.w*inv5 - mw*mw;

    // stage variance to smem: sv[c][w_local]
    __shared__ float sv[32][33];
    sv[4*q+0][p] = var.x;
    sv[4*q+1][p] = var.y;
    sv[4*q+2][p] = var.z;
    sv[4*q+3][p] = var.w;
    __syncthreads();

    // ---- Phase B: 27x32x32 contraction, A_j[w] = sum_c W[c][j]*var[c][w] ----
    float acc0 = 0.f, acc1 = 0.f, acc2 = 0.f, acc3 = 0.f;
    #pragma unroll
    for (int c = 0; c < 32; c++) {
        float f = sv[c][lane];
        acc0 += f * __shfl_sync(0xffffffffu, wreg[0], c);
        acc1 += f * __shfl_sync(0xffffffffu, wreg[1], c);
        acc2 += f * __shfl_sync(0xffffffffu, wreg[2], c);
        acc3 += f * __shfl_sync(0xffffffffu, wreg[3], c);
    }
    size_t obase = (size_t)d*HW + (size_t)h*NW + w0 + lane;
    g_A[(size_t)(wid     )*DHW + obase] = acc0;
    g_A[(size_t)(wid +  8)*DHW + obase] = acc1;
    g_A[(size_t)(wid + 16)*DHW + obase] = acc2;
    if (wid < 3)
        g_A[(size_t)(wid + 24)*DHW + obase] = acc3;
}

// ---------------------------------------------------------------------------
// 4) Shifted 27-tap sum: pre[x] = sum_j A_j[x + off_j]  (SAME zero padding)
// ---------------------------------------------------------------------------
__global__ __launch_bounds__(256) void gathersum_kernel() {
    int w = blockIdx.x*32 + threadIdx.x;
    int h = blockIdx.y*8  + threadIdx.y;
    int d = blockIdx.z;
    float s = 0.f;
    #pragma unroll
    for (int kd = 0; kd < 3; kd++) {
        int dd = d + kd - 1;
        if (dd < 0 || dd >= ND) continue;
        #pragma unroll
        for (int kh = 0; kh < 3; kh++) {
            int hh = h + kh - 1;
            if (hh < 0 || hh >= NH) continue;
            size_t rowb = (size_t)dd*HW + (size_t)hh*NW;
            #pragma unroll
            for (int kw = 0; kw < 3; kw++) {
                int ww = w + kw - 1;
                if (ww < 0 || ww >= NW) continue;
                int j = kd*9 + kh*3 + kw;
                s += g_A[(size_t)j*DHW + rowb + ww];
            }
        }
    }
    g_pre[(size_t)d*HW + (size_t)h*NW + w] = s;
}

// ---------------------------------------------------------------------------
// 5) Softmax over D + depth regression + confidence
// ---------------------------------------------------------------------------
__global__ __launch_bounds__(256) void sdc_kernel(const float* __restrict__ dvals,
                                                  float* __restrict__ odepth,
                                                  float* __restrict__ oconf) {
    int idx = blockIdx.x*blockDim.x + threadIdx.x;
    if (idx >= HW) return;
    float p[ND];
    float mx = -1e30f;
    #pragma unroll
    for (int dd = 0; dd < ND; dd++) { p[dd] = g_pre[(size_t)dd*HW + idx]; mx = fmaxf(mx, p[dd]); }
    float s = 0.f;
    #pragma unroll
    for (int dd = 0; dd < ND; dd++) { p[dd] = expf(p[dd] - mx); s += p[dd]; }
    float inv = 1.f / s;
    float depth = 0.f, fi = 0.f;
    #pragma unroll
    for (int dd = 0; dd < ND; dd++) {
        float pr = p[dd] * inv;
        depth += pr * dvals[dd];
        fi    += pr * (float)dd;
    }
    int di = (int)fi;
    di = max(0, min(ND-1, di));
    float conf = 0.f;
    #pragma unroll
    for (int dd = 0; dd < ND; dd++)
        if (dd >= di-1 && dd <= di+2) conf += p[dd] * inv;
    odepth[idx] = depth;
    oconf[idx]  = conf;
}

// ---------------------------------------------------------------------------
// 6) Convex upsample x8
// ---------------------------------------------------------------------------
__global__ __launch_bounds__(256) void upsample_kernel(const float* __restrict__ mask,
                                                       const float* __restrict__ depth,
                                                       float* __restrict__ out) {
    int idx = blockIdx.x*blockDim.x + threadIdx.x;
    if (idx >= RATIO*HW) return;
    int i   = idx / HW;
    int rem = idx - i*HW;
    int h   = rem / NW;
    int w   = rem - h*NW;

    float nb[9];
    #pragma unroll
    for (int dy = 0; dy < 3; dy++)
        #pragma unroll
        for (int dx = 0; dx < 3; dx++) {
            int hh = h + dy - 1, ww = w + dx - 1;
            nb[dy*3+dx] = (hh >= 0 && hh < NH && ww >= 0 && ww < NW) ? depth[hh*NW + ww] : 0.f;
        }

    float val[8];
    #pragma unroll
    for (int j = 0; j < 8; j++) {
        float m[9]; float mx = -1e30f;
        #pragma unroll
        for (int k = 0; k < 9; k++) {
            m[k] = mask[(size_t)((k*8 + i)*8 + j)*HW + rem];
            mx = fmaxf(mx, m[k]);
        }
        float s = 0.f, acc = 0.f;
        #pragma unroll
        for (int k = 0; k < 9; k++) {
            float e = __expf(m[k] - mx);
            s += e; acc += e * nb[k];
        }
        val[j] = acc / s;
    }
    float* o = out + (size_t)(h*8 + i)*(NW*8) + w*8;
    float4* o4 = (float4*)o;
    o4[0] = make_float4(val[0], val[1], val[2], val[3]);
    o4[1] = make_float4(val[4], val[5], val[6], val[7]);
}

// ---------------------------------------------------------------------------
extern "C" void kernel_launch(void* const* d_in, const int* in_sizes, int n_in,
                              void* d_out, int out_size) {
    const float* features = (const float*)d_in[0];  // (V,B,C,H,W)
    const float* proj     = (const float*)d_in[1];  // (B,V,2,4,4)
    const float* dvals    = (const float*)d_in[2];  // (B,D)
    const float* mask     = (const float*)d_in[3];  // (B,576,H,W)
    const float* Wreg     = (const float*)d_in[4];  // (1,C,3,3,3)

    float* out       = (float*)d_out;
    float* out_depth = out + (size_t)NH*RATIO*NW*RATIO;   // after depth_up
    float* out_conf  = out_depth + HW;

    proj_kernel<<<1, 32>>>(proj);
    transpose_kernel<<<dim3(NW/32, NH, NV), 256>>>(features);
    warpvar_kernel<<<dim3(NW/32, NH, ND), 256>>>(dvals, Wreg);
    gathersum_kernel<<<dim3(NW/32, NH/8, ND), dim3(32, 8)>>>();
    sdc_kernel<<<HW/256, 256>>>(dvals, out_depth, out_conf);
    upsample_kernel<<<(RATIO*HW)/256, 256>>>(mask, out_depth, out);
}

// round 3
// speedup vs baseline: 1.3174x; 1.2727x over previous
#include <cuda_runtime.h>

#define NV 5
#define NC 32
#define ND 48
#define NH 128
#define NW 160
#define HW (NH*NW)        /* 20480 */
#define DHW (ND*HW)       /* 983040 */
#define RATIO 8

// Scratch (device globals — no allocation allowed)
__device__ float g_feat[NV*HW*NC];          // (v, h, w, c) channels-last, 13.1 MB
__device__ float g_A[(size_t)27*DHW];       // 27 tap-fields (j, d, h, w), 106 MB
__device__ float g_pre[DHW];                // (d, h, w), 3.9 MB
__device__ float g_rot[NV][9];
__device__ float g_trans[NV][3];

// ---------------------------------------------------------------------------
// 1) Projection setup (trivial)
// ---------------------------------------------------------------------------
__global__ void proj_kernel(const float* __restrict__ proj) {
    if (threadIdx.x != 0) return;
    float comb[NV][16];
    for (int v = 0; v < NV; v++) {
        const float* E = proj + v*32;
        const float* P = proj + v*32 + 16;
        for (int r = 0; r < 3; r++)
            for (int c = 0; c < 4; c++) {
                float s = 0.f;
                for (int k = 0; k < 3; k++) s += P[r*4+k] * E[k*4+c];
                comb[v][r*4+c] = s;
            }
        for (int c = 0; c < 4; c++) comb[v][12+c] = E[12+c];
    }
    float a[4][8];
    for (int i = 0; i < 4; i++)
        for (int j = 0; j < 4; j++) { a[i][j] = comb[0][i*4+j]; a[i][4+j] = (i==j) ? 1.f : 0.f; }
    for (int col = 0; col < 4; col++) {
        int p = col;
        for (int r = col+1; r < 4; r++) if (fabsf(a[r][col]) > fabsf(a[p][col])) p = r;
        if (p != col) for (int j = 0; j < 8; j++) { float t = a[col][j]; a[col][j] = a[p][j]; a[p][j] = t; }
        float inv = 1.f / a[col][col];
        for (int j = 0; j < 8; j++) a[col][j] *= inv;
        for (int r = 0; r < 4; r++) if (r != col) {
            float f = a[r][col];
            for (int j = 0; j < 8; j++) a[r][j] -= f * a[col][j];
        }
    }
    for (int v = 1; v < NV; v++) {
        float Pm[16];
        for (int i = 0; i < 4; i++)
            for (int j = 0; j < 4; j++) {
                float s = 0.f;
                for (int k = 0; k < 4; k++) s += comb[v][i*4+k] * a[k][4+j];
                Pm[i*4+j] = s;
            }
        for (int i = 0; i < 3; i++) {
            for (int j = 0; j < 3; j++) g_rot[v][i*3+j] = Pm[i*4+j];
            g_trans[v][i] = Pm[i*4+3];
        }
    }
}

// ---------------------------------------------------------------------------
// 2) Features (V,C,H,W) -> (V,H,W,C) channels-last
// ---------------------------------------------------------------------------
__global__ __launch_bounds__(256) void transpose_kernel(const float* __restrict__ f) {
    __shared__ float t[32][33];
    int w0 = blockIdx.x * 32, h = blockIdx.y, v = blockIdx.z;
    int tid = threadIdx.x;
    #pragma unroll
    for (int e = tid; e < 1024; e += 256) {
        int c = e >> 5, w = e & 31;
        t[c][w] = f[((size_t)(v*NC + c)*NH + h)*NW + w0 + w];
    }
    __syncthreads();
    #pragma unroll
    for (int e = tid; e < 1024; e += 256) {
        int w = e >> 5, c = e & 31;
        g_feat[((size_t)((v*NH + h)*NW) + w0 + w)*NC + c] = t[c][w];
    }
}

// ---------------------------------------------------------------------------
// 3) FUSED: homography warp + variance + channel contraction, ALL 48 depths
//    per CTA.  One CTA = 32-w strip at fixed h; loops d = 0..47.
//    Phase A: per-voxel variance; lane = (sub,q): sub picks 1 of 4 points per
//             warp, q picks a float4 channel-quad -> warp LDG.128 covers 4
//             full 128B feature lines.
//    Phase B: A_j[w] = sum_c W[c][j]*var[c][w]; warp wid owns js 4wid..4wid+3
//             with ALL 128 weights resident in registers (loaded once per
//             CTA, amortized over 48 depths).  Inner loop: 1 LDS + 4 FFMA.
// ---------------------------------------------------------------------------
__global__ __launch_bounds__(256, 1) void warpvar_kernel(const float* __restrict__ dvals,
                                                         const float* __restrict__ Wreg) {
    int tid  = threadIdx.x;
    int lane = tid & 31, wid = tid >> 5;
    int sub = lane >> 3, q = lane & 7;
    int p  = wid * 4 + sub;              // point 0..31
    int w0 = blockIdx.x * 32;
    int h  = blockIdx.y;
    int w  = w0 + p;

    // ---- one-time weight preload: W[c][j] for j = 4*wid + jj ----
    float wt[4][32];
    #pragma unroll
    for (int jj = 0; jj < 4; jj++) {
        int j = wid*4 + jj;
        #pragma unroll
        for (int c = 0; c < 32; c++)
            wt[jj][c] = (j < 27) ? Wreg[c*27 + j] : 0.f;
    }

    // ---- depth values to smem ----
    __shared__ float sdep[ND];
    if (tid < ND) sdep[tid] = dvals[tid];

    // ---- per-view projection precompute (w,h fixed for the whole CTA) ----
    float fw = (float)w, fh = (float)h;
    float rx[NV-1], ry[NV-1], rz[NV-1], tx[NV-1], ty[NV-1], tz[NV-1];
    #pragma unroll
    for (int v = 1; v < NV; v++) {
        const float* R = g_rot[v];
        const float* T = g_trans[v];
        rx[v-1] = R[0]*fw + R[1]*fh + R[2];
        ry[v-1] = R[3]*fw + R[4]*fh + R[5];
        rz[v-1] = R[6]*fw + R[7]*fh + R[8];
        tx[v-1] = T[0]; ty[v-1] = T[1]; tz[v-1] = T[2];
    }

    // ---- reference view contribution (depth-independent) ----
    const float4* f0 = (const float4*)(g_feat + (size_t)(h*NW + w)*NC) + q;
    float4 ref = *f0;
    float4 ref2 = make_float4(ref.x*ref.x, ref.y*ref.y, ref.z*ref.z, ref.w*ref.w);

    __shared__ float sv[32][33];
    const float inv5 = 1.f / (float)NV;

    __syncthreads();   // sdep ready

    for (int d = 0; d < ND; d++) {
        float dep = sdep[d];
        float4 vs = ref;
        float4 vq = ref2;
        #pragma unroll
        for (int v = 0; v < NV-1; v++) {
            float px = rx[v]*dep + tx[v];
            float py = ry[v]*dep + ty[v];
            float pz = rz[v]*dep + tz[v];
            float rzi = __fdividef(1.f, pz);
            float gx = px * rzi, gy = py * rzi;
            float x0f = floorf(gx), y0f = floorf(gy);
            float wx = gx - x0f, wy = gy - y0f;
            float x1f = x0f + 1.f, y1f = y0f + 1.f;
            float vx0 = (x0f >= 0.f && x0f <= (float)(NW-1)) ? 1.f : 0.f;
            float vx1 = (x1f >= 0.f && x1f <= (float)(NW-1)) ? 1.f : 0.f;
            float vy0 = (y0f >= 0.f && y0f <= (float)(NH-1)) ? 1.f : 0.f;
            float vy1 = (y1f >= 0.f && y1f <= (float)(NH-1)) ? 1.f : 0.f;
            float w00 = (1.f-wx)*(1.f-wy) * vx0 * vy0;
            float w10 = wx*(1.f-wy)       * vx1 * vy0;
            float w01 = (1.f-wx)*wy       * vx0 * vy1;
            float w11 = wx*wy             * vx1 * vy1;
            int x0 = (int)fminf(fmaxf(x0f, 0.f), (float)(NW-1));
            int x1 = (int)fminf(fmaxf(x1f, 0.f), (float)(NW-1));
            int y0 = (int)fminf(fmaxf(y0f, 0.f), (float)(NH-1));
            int y1 = (int)fminf(fmaxf(y1f, 0.f), (float)(NH-1));
            const float* base = g_feat + (size_t)(v+1)*HW*NC;
            float4 a  = ((const float4*)(base + (size_t)(y0*NW + x0)*NC))[q];
            float4 b  = ((const float4*)(base + (size_t)(y0*NW + x1)*NC))[q];
            float4 c4 = ((const float4*)(base + (size_t)(y1*NW + x0)*NC))[q];
            float4 e4 = ((const float4*)(base + (size_t)(y1*NW + x1)*NC))[q];
            float4 wv;
            wv.x = w00*a.x + w10*b.x + w01*c4.x + w11*e4.x;
            wv.y = w00*a.y + w10*b.y + w01*c4.y + w11*e4.y;
            wv.z = w00*a.z + w10*b.z + w01*c4.z + w11*e4.z;
            wv.w = w00*a.w + w10*b.w + w01*c4.w + w11*e4.w;
            vs.x += wv.x; vs.y += wv.y; vs.z += wv.z; vs.w += wv.w;
            vq.x += wv.x*wv.x; vq.y += wv.y*wv.y; vq.z += wv.z*wv.z; vq.w += wv.w*wv.w;
        }
        float mx = vs.x*inv5, my = vs.y*inv5, mz = vs.z*inv5, mw = vs.w*inv5;
        float vvx = vq.x*inv5 - mx*mx;
        float vvy = vq.y*inv5 - my*my;
        float vvz = vq.z*inv5 - mz*mz;
        float vvw = vq.w*inv5 - mw*mw;

        __syncthreads();   // previous iteration's Phase B reads complete
        sv[4*q+0][p] = vvx;
        sv[4*q+1][p] = vvy;
        sv[4*q+2][p] = vvz;
        sv[4*q+3][p] = vvw;
        __syncthreads();

        // ---- Phase B: 1 LDS + 4 register-weight FFMA per channel ----
        float acc0 = 0.f, acc1 = 0.f, acc2 = 0.f, acc3 = 0.f;
        #pragma unroll
        for (int c = 0; c < 32; c++) {
            float f = sv[c][lane];
            acc0 += f * wt[0][c];
            acc1 += f * wt[1][c];
            acc2 += f * wt[2][c];
            acc3 += f * wt[3][c];
        }
        size_t obase = (size_t)d*HW + (size_t)h*NW + w0 + lane;
        int jb = wid*4;
        if (jb     < 27) g_A[(size_t)(jb    )*DHW + obase] = acc0;
        if (jb + 1 < 27) g_A[(size_t)(jb + 1)*DHW + obase] = acc1;
        if (jb + 2 < 27) g_A[(size_t)(jb + 2)*DHW + obase] = acc2;
        if (jb + 3 < 27) g_A[(size_t)(jb + 3)*DHW + obase] = acc3;
    }
}

// ---------------------------------------------------------------------------
// 4) Shifted 27-tap sum: pre[x] = sum_j A_j[x + off_j]  (SAME zero padding)
// ---------------------------------------------------------------------------
__global__ __launch_bounds__(256) void gathersum_kernel() {
    int w = blockIdx.x*32 + threadIdx.x;
    int h = blockIdx.y*8  + threadIdx.y;
    int d = blockIdx.z;
    float s = 0.f;
    #pragma unroll
    for (int kd = 0; kd < 3; kd++) {
        int dd = d + kd - 1;
        if (dd < 0 || dd >= ND) continue;
        #pragma unroll
        for (int kh = 0; kh < 3; kh++) {
            int hh = h + kh - 1;
            if (hh < 0 || hh >= NH) continue;
            size_t rowb = (size_t)dd*HW + (size_t)hh*NW;
            #pragma unroll
            for (int kw = 0; kw < 3; kw++) {
                int ww = w + kw - 1;
                if (ww < 0 || ww >= NW) continue;
                int j = kd*9 + kh*3 + kw;
                s += g_A[(size_t)j*DHW + rowb + ww];
            }
        }
    }
    g_pre[(size_t)d*HW + (size_t)h*NW + w] = s;
}

// ---------------------------------------------------------------------------
// 5) Softmax over D + depth regression + confidence
// ---------------------------------------------------------------------------
__global__ __launch_bounds__(256) void sdc_kernel(const float* __restrict__ dvals,
                                                  float* __restrict__ odepth,
                                                  float* __restrict__ oconf) {
    int idx = blockIdx.x*blockDim.x + threadIdx.x;
    if (idx >= HW) return;
    float p[ND];
    float mx = -1e30f;
    #pragma unroll
    for (int dd = 0; dd < ND; dd++) { p[dd] = g_pre[(size_t)dd*HW + idx]; mx = fmaxf(mx, p[dd]); }
    float s = 0.f;
    #pragma unroll
    for (int dd = 0; dd < ND; dd++) { p[dd] = expf(p[dd] - mx); s += p[dd]; }
    float inv = 1.f / s;
    float depth = 0.f, fi = 0.f;
    #pragma unroll
    for (int dd = 0; dd < ND; dd++) {
        float pr = p[dd] * inv;
        depth += pr * dvals[dd];
        fi    += pr * (float)dd;
    }
    int di = (int)fi;
    di = max(0, min(ND-1, di));
    float conf = 0.f;
    #pragma unroll
    for (int dd = 0; dd < ND; dd++)
        if (dd >= di-1 && dd <= di+2) conf += p[dd] * inv;
    odepth[idx] = depth;
    oconf[idx]  = conf;
}

// ---------------------------------------------------------------------------
// 6) Convex upsample x8
// ---------------------------------------------------------------------------
__global__ __launch_bounds__(256) void upsample_kernel(const float* __restrict__ mask,
                                                       const float* __restrict__ depth,
                                                       float* __restrict__ out) {
    int idx = blockIdx.x*blockDim.x + threadIdx.x;
    if (idx >= RATIO*HW) return;
    int i   = idx / HW;
    int rem = idx - i*HW;
    int h   = rem / NW;
    int w   = rem - h*NW;

    float nb[9];
    #pragma unroll
    for (int dy = 0; dy < 3; dy++)
        #pragma unroll
        for (int dx = 0; dx < 3; dx++) {
            int hh = h + dy - 1, ww = w + dx - 1;
            nb[dy*3+dx] = (hh >= 0 && hh < NH && ww >= 0 && ww < NW) ? depth[hh*NW + ww] : 0.f;
        }

    float val[8];
    #pragma unroll
    for (int j = 0; j < 8; j++) {
        float m[9]; float mx = -1e30f;
        #pragma unroll
        for (int k = 0; k < 9; k++) {
            m[k] = mask[(size_t)((k*8 + i)*8 + j)*HW + rem];
            mx = fmaxf(mx, m[k]);
        }
        float s = 0.f, acc = 0.f;
        #pragma unroll
        for (int k = 0; k < 9; k++) {
            float e = __expf(m[k] - mx);
            s += e; acc += e * nb[k];
        }
        val[j] = acc / s;
    }
    float* o = out + (size_t)(h*8 + i)*(NW*8) + w*8;
    float4* o4 = (float4*)o;
    o4[0] = make_float4(val[0], val[1], val[2], val[3]);
    o4[1] = make_float4(val[4], val[5], val[6], val[7]);
}

// ---------------------------------------------------------------------------
extern "C" void kernel_launch(void* const* d_in, const int* in_sizes, int n_in,
                              void* d_out, int out_size) {
    const float* features = (const float*)d_in[0];  // (V,B,C,H,W)
    const float* proj     = (const float*)d_in[1];  // (B,V,2,4,4)
    const float* dvals    = (const float*)d_in[2];  // (B,D)
    const float* mask     = (const float*)d_in[3];  // (B,576,H,W)
    const float* Wreg     = (const float*)d_in[4];  // (1,C,3,3,3)

    float* out       = (float*)d_out;
    float* out_depth = out + (size_t)NH*RATIO*NW*RATIO;   // after depth_up
    float* out_conf  = out_depth + HW;

    proj_kernel<<<1, 32>>>(proj);
    transpose_kernel<<<dim3(NW/32, NH, NV), 256>>>(features);
    warpvar_kernel<<<dim3(NW/32, NH), 256>>>(dvals, Wreg);
    gathersum_kernel<<<dim3(NW/32, NH/8, ND), dim3(32, 8)>>>();
    sdc_kernel<<<HW/256, 256>>>(dvals, out_depth, out_conf);
    upsample_kernel<<<(RATIO*HW)/256, 256>>>(mask, out_depth, out);
}